// round 15
// baseline (speedup 1.0000x reference)
#include <cuda_runtime.h>
#include <cuda_fp16.h>
#include <cstdint>

// ---------------- problem constants ----------------
#define CC 384
#define NHEAD 12
#define HD 32
#define NTOK 64
#define NWIN 1024
#define TOK 65536
#define HMLP 1536
#define QSCALE 0.17677669529663687f   // 32^-0.5

// ---------------- scratch (device globals; no allocations) ----------------
__device__ __half g_xw [TOK * CC];      // activations: fp16
__device__ __half g_ao [TOK * CC];
__device__ __half g_ln2[TOK * CC];
__device__ __half g_mlp[TOK * HMLP];
__device__ __half g_wqkv[3*CC*CC];      // weights: single fp16
__device__ __half g_wp [CC*CC];
__device__ __half g_w1 [HMLP*CC];
__device__ __half g_w2 [CC*HMLP];
__device__ __half g_q [TOK * CC];       // fp16 q (pre-scaled), k, v
__device__ __half g_k [TOK * CC];
__device__ __half g_v [TOK * CC];
__device__ float g_x2[TOK * CC];
__device__ float g_T [8 * NHEAD * NTOK * NTOK];   // bias+mask per window class

// ---------------- helpers ----------------
__device__ __forceinline__ uint32_t smem_u32(const void* p) {
    uint32_t a;
    asm("{ .reg .u64 t; cvta.to.shared.u64 t, %1; cvt.u32.u64 %0, t; }" : "=r"(a) : "l"(p));
    return a;
}
__device__ __forceinline__ void cp16(uint32_t saddr, const void* gaddr) {
    asm volatile("cp.async.cg.shared.global [%0], [%1], 16;" :: "r"(saddr), "l"(gaddr));
}
__device__ __forceinline__ void ldm4(uint32_t* r, uint32_t addr) {
    asm volatile("ldmatrix.sync.aligned.m8n8.x4.shared.b16 {%0,%1,%2,%3}, [%4];"
                 : "=r"(r[0]), "=r"(r[1]), "=r"(r[2]), "=r"(r[3]) : "r"(addr));
}
__device__ __forceinline__ void ldm4t(uint32_t* r, uint32_t addr) {
    asm volatile("ldmatrix.sync.aligned.m8n8.x4.trans.shared.b16 {%0,%1,%2,%3}, [%4];"
                 : "=r"(r[0]), "=r"(r[1]), "=r"(r[2]), "=r"(r[3]) : "r"(addr));
}
__device__ __forceinline__ void mma16816(float* c, const uint32_t* a, const uint32_t* b) {
    asm volatile("mma.sync.aligned.m16n8k16.row.col.f32.f16.f16.f32 "
                 "{%0,%1,%2,%3}, {%4,%5,%6,%7}, {%8,%9}, {%0,%1,%2,%3};"
                 : "+f"(c[0]), "+f"(c[1]), "+f"(c[2]), "+f"(c[3])
                 : "r"(a[0]), "r"(a[1]), "r"(a[2]), "r"(a[3]), "r"(b[0]), "r"(b[1]));
}
__device__ __forceinline__ uint32_t packh2(float a, float b) {
    __half2 h = __floats2half2_rn(a, b);
    return *(uint32_t*)&h;
}

// ---------------- fused weight fp32 -> fp16 ----------
#define NW0 (3*CC*CC)
#define NW1 (NW0 + CC*CC)
#define NW2 (NW1 + HMLP*CC)
#define NW3 (NW2 + CC*HMLP)
__global__ __launch_bounds__(256) void cvt_all(const float* __restrict__ wqkv,
                                               const float* __restrict__ wp,
                                               const float* __restrict__ w1,
                                               const float* __restrict__ w2) {
    int i = blockIdx.x * 256 + threadIdx.x;
    if (i >= NW3) return;
    const float* src; __half* dh; int o;
    if (i < NW0)      { src = wqkv; dh = g_wqkv; o = i; }
    else if (i < NW1) { src = wp;   dh = g_wp;   o = i - NW0; }
    else if (i < NW2) { src = w1;   dh = g_w1;   o = i - NW1; }
    else              { src = w2;   dh = g_w2;   o = i - NW2; }
    dh[o] = __float2half_rn(src[o]);
}

// ---------------- bias+mask table: T[cls][h][q][k] ----------
__global__ __launch_bounds__(256) void build_T(const float* __restrict__ bt) {
    int cls = blockIdx.x, h = blockIdx.y;
    bool bd = cls & 4, bh = cls & 2, bw = cls & 1;
    for (int e = threadIdx.x; e < NTOK * NTOK; e += 256) {
        int q = e >> 6, k = e & 63;
        int i = q >> 4, j = (q >> 2) & 3, kk = q & 3;
        int i2 = k >> 4, j2 = (k >> 2) & 3, k2 = k & 3;
        int idx = (i - i2 + 3) * 49 + (j - j2 + 3) * 7 + (kk - k2 + 3);
        bool m = (!bd || ((i < 2) == (i2 < 2))) &&
                 (!bh || ((j < 2) == (j2 < 2))) &&
                 (!bw || ((kk < 2) == (k2 < 2)));
        g_T[(((size_t)cls * NHEAD + h) << 12) + e] = bt[idx * NHEAD + h] + (m ? 0.f : -100.f);
    }
}

// ---------------- LayerNorm ----------------
template<int MODE>
__global__ __launch_bounds__(128) void ln_kernel(const float* __restrict__ xin,
                                                 const float* __restrict__ gamma,
                                                 const float* __restrict__ beta)
{
    int t = blockIdx.x;
    const float* src;
    __half* dh;
    if constexpr (MODE == 0) {
        int g = t >> 6, n = t & 63;
        int b = g >> 9, wd = (g >> 6) & 7, wh = (g >> 3) & 7, ww = g & 7;
        int i = n >> 4, j = (n >> 2) & 3, k = n & 3;
        int d0 = (wd * 4 + i + 2) & 31;
        int h0 = (wh * 4 + j + 2) & 31;
        int w0 = (ww * 4 + k + 2) & 31;
        src = xin + (size_t)(((b * 32 + d0) * 32 + h0) * 32 + w0) * CC;
        dh = g_xw + (size_t)t * CC;
    } else {
        src = g_x2 + (size_t)t * CC;
        dh = g_ln2 + (size_t)t * CC;
    }
    int tid = threadIdx.x;
    float v0 = src[tid], v1 = src[tid + 128], v2 = src[tid + 256];
    float s = v0 + v1 + v2;
    float ss = v0 * v0 + v1 * v1 + v2 * v2;
    #pragma unroll
    for (int o = 16; o > 0; o >>= 1) {
        s  += __shfl_xor_sync(0xffffffffu, s, o);
        ss += __shfl_xor_sync(0xffffffffu, ss, o);
    }
    __shared__ float red[8];
    if ((tid & 31) == 0) { red[tid >> 5] = s; red[4 + (tid >> 5)] = ss; }
    __syncthreads();
    s  = red[0] + red[1] + red[2] + red[3];
    ss = red[4] + red[5] + red[6] + red[7];
    float mu  = s * (1.0f / CC);
    float var = ss * (1.0f / CC) - mu * mu;
    float inv = rsqrtf(var + 1e-5f);
    dh[tid]       = __float2half_rn((v0 - mu) * inv * gamma[tid]       + beta[tid]);
    dh[tid + 128] = __float2half_rn((v1 - mu) * inv * gamma[tid + 128] + beta[tid + 128]);
    dh[tid + 256] = __float2half_rn((v2 - mu) * inv * gamma[tid + 256] + beta[tid + 256]);
}

// ---------------- mma.sync fp16 GEMM: C = A @ B^T + bias ------
// 128x128 CTA tile, BK=32, 4-stage cp.async ring (wait_group 2); 2 CTAs/SM.
#define STG_A   0
#define STG_B   10240
#define STG_SZ  20480
#define NSTAGE  4

template<int EPI, int N, int K>
__global__ __launch_bounds__(256, 2) void tgemm(const float* __restrict__ bias,
                                                float* __restrict__ Cout,
                                                const float* __restrict__ extra)
{
    const __half *A, *B;
    if constexpr (EPI == 0)      { A = g_xw;  B = g_wqkv; }
    else if constexpr (EPI == 1) { A = g_ao;  B = g_wp;   }
    else if constexpr (EPI == 2) { A = g_ln2; B = g_w1;   }
    else                         { A = g_mlp; B = g_w2;   }

    extern __shared__ char smem[];
    const uint32_t sb = smem_u32(smem);
    const int tid = threadIdx.x;
    const int wid = tid >> 5, lane = tid & 31;
    const int wm = wid & 1, wn = wid >> 1;
    const int m0 = blockIdx.y * 128, n0 = blockIdx.x * 128;
    constexpr int NC = K / 32;

    auto issue = [&](int c, int st) {
        int k0 = c * 32;
        uint32_t base = sb + (uint32_t)st * STG_SZ;
        #pragma unroll
        for (int t = 0; t < 2; t++) {
            int e = tid + t * 256;
            int r = e >> 2, cv = e & 3;
            uint32_t so = (uint32_t)(r * 80 + cv * 16);
            size_t ga = (size_t)(m0 + r) * K + k0 + cv * 8;
            size_t gb = (size_t)(n0 + r) * K + k0 + cv * 8;
            cp16(base + STG_A + so, A + ga);
            cp16(base + STG_B + so, B + gb);
        }
        asm volatile("cp.async.commit_group;");
    };

    const int lr = lane & 7;
    const int aRow = wm * 64 + lr + ((lane >> 3) & 1) * 8;
    const int aK   = (lane >> 4) * 8;
    const int bRow = wn * 32 + lr + (lane >> 4) * 8;
    const int bK   = ((lane >> 3) & 1) * 8;

    float acc[4][4][4];
    #pragma unroll
    for (int a = 0; a < 4; a++)
        #pragma unroll
        for (int b = 0; b < 4; b++)
            #pragma unroll
            for (int c = 0; c < 4; c++) acc[a][b][c] = 0.f;

    issue(0, 0);
    if (NC > 1) issue(1, 1);
    if (NC > 2) issue(2, 2);

    for (int c = 0; c < NC; c++) {
        if (c >= NC - 3)      asm volatile("cp.async.wait_group 0;" ::: "memory");
        else if (c == NC - 3) asm volatile("cp.async.wait_group 1;" ::: "memory");
        else                  asm volatile("cp.async.wait_group 2;" ::: "memory");
        __syncthreads();
        if (c + 3 < NC) issue(c + 3, (c + 3) % NSTAGE);

        uint32_t base = sb + (uint32_t)(c % NSTAGE) * STG_SZ;
        #pragma unroll
        for (int ks = 0; ks < 2; ks++) {
            uint32_t a_r[4][4];
            #pragma unroll
            for (int mt = 0; mt < 4; mt++) {
                uint32_t off = (uint32_t)((aRow + mt * 16) * 40 + ks * 16 + aK) * 2;
                ldm4(a_r[mt], base + STG_A + off);
            }
            uint32_t b_r[4][2];
            #pragma unroll
            for (int p = 0; p < 2; p++) {
                uint32_t off = (uint32_t)((bRow + p * 16) * 40 + ks * 16 + bK) * 2;
                uint32_t r4[4];
                ldm4(r4, base + STG_B + off);
                b_r[2*p][0] = r4[0]; b_r[2*p][1] = r4[1];
                b_r[2*p+1][0] = r4[2]; b_r[2*p+1][1] = r4[3];
            }
            #pragma unroll
            for (int mt = 0; mt < 4; mt++)
                #pragma unroll
                for (int nt = 0; nt < 4; nt++) mma16816(acc[mt][nt], a_r[mt], b_r[nt]);
        }
    }

    // ---------------- epilogue ----------------
    const int mrow0 = m0 + wm * 64 + (lane >> 2);
    const int ncol0 = n0 + wn * 32 + (lane & 3) * 2;

    #pragma unroll
    for (int mt = 0; mt < 4; mt++) {
        #pragma unroll
        for (int nt = 0; nt < 4; nt++) {
            #pragma unroll
            for (int half = 0; half < 2; half++) {
                int row = mrow0 + mt * 16 + half * 8;
                int col = ncol0 + nt * 8;
                float v0 = acc[mt][nt][half * 2]     + bias[col];
                float v1 = acc[mt][nt][half * 2 + 1] + bias[col + 1];

                if constexpr (EPI == 0) {
                    int s = col / CC; int rr = col - s * CC;
                    int hh = rr >> 5, d = rr & 31;
                    __half* dst = (s == 0) ? g_q : (s == 1) ? g_k : g_v;
                    if (s == 0) { v0 *= QSCALE; v1 *= QSCALE; }
                    size_t o = (((size_t)(row >> 6) * NHEAD + hh) * NTOK + (row & 63)) * HD + d;
                    *(uint32_t*)(dst + o) = packh2(v0, v1);
                } else if constexpr (EPI == 1) {
                    int g = row >> 6, nn = row & 63;
                    int b = g >> 9, wd = (g >> 6) & 7, wh = (g >> 3) & 7, ww = g & 7;
                    int i3 = nn >> 4, j3 = (nn >> 2) & 3, k3 = nn & 3;
                    int d0 = (wd * 4 + i3 + 2) & 31;
                    int h0 = (wh * 4 + j3 + 2) & 31;
                    int w0 = (ww * 4 + k3 + 2) & 31;
                    size_t nat = (size_t)(((b * 32 + d0) * 32 + h0) * 32 + w0) * CC + col;
                    float2 e = *(const float2*)(extra + nat);
                    *(float2*)(g_x2 + nat) = make_float2(v0 + e.x, v1 + e.y);
                } else if constexpr (EPI == 2) {
                    size_t o = (size_t)row * HMLP + col;
                    float t0 = v0 * 0.5f * (1.0f + erff(v0 * 0.70710678118654752f));
                    float t1 = v1 * 0.5f * (1.0f + erff(v1 * 0.70710678118654752f));
                    *(uint32_t*)(g_mlp + o) = packh2(t0, t1);
                } else {
                    size_t o = (size_t)row * CC + col;
                    float2 e = *(const float2*)(g_x2 + o);
                    *(float2*)(Cout + o) = make_float2(v0 + e.x, v1 + e.y);
                }
            }
        }
    }
}

// ---------------- mma attention: 1 block = 1 window, 4 warps x 3 heads -----
// K/V staged in warp-private smem; Q fragments loaded directly from global.
#define AT_WSZ  10240   // per-warp smem: K + V (2 x 64x40 halves)
#define AT_SMEM (4 * AT_WSZ)

__global__ __launch_bounds__(128) void attn_kernel()
{
    extern __shared__ char asmem[];
    int g = blockIdx.x;
    int tid = threadIdx.x, w = tid >> 5, lane = tid & 31;
    int wd = (g >> 6) & 7, wh = (g >> 3) & 7, ww = g & 7;
    int cls = ((wd == 7) << 2) | ((wh == 7) << 1) | (ww == 7);
    uint32_t wb = smem_u32(asmem) + (uint32_t)w * AT_WSZ;
    uint32_t sK = wb, sV = wb + 5120;

    const int qr = lane >> 2;
    const int c0 = (lane & 3) * 2;

    for (int hh = 0; hh < 3; hh++) {
        int h = w * 3 + hh;
        const __half* qb = g_q + (size_t)(g * NHEAD + h) * NTOK * HD;
        const __half* kb = g_k + (size_t)(g * NHEAD + h) * NTOK * HD;
        const __half* vb = g_v + (size_t)(g * NHEAD + h) * NTOK * HD;
        #pragma unroll
        for (int t = 0; t < 8; t++) {
            int e = lane + t * 32;
            int r = e >> 2, c = e & 3;
            cp16(sK + r * 80 + c * 16, kb + r * 32 + c * 8);
            cp16(sV + r * 80 + c * 16, vb + r * 32 + c * 8);
        }
        asm volatile("cp.async.commit_group;");
        asm volatile("cp.async.wait_group 0;");
        __syncwarp();

        uint32_t bv[4][4][2];
        #pragma unroll
        for (int kt = 0; kt < 4; kt++)
            #pragma unroll
            for (int nh = 0; nh < 2; nh++) {
                uint32_t r4[4];
                uint32_t addr = sV + (uint32_t)((kt * 16 + (lane & 15)) * 80
                                                + (nh * 16 + (lane >> 4) * 8) * 2);
                ldm4t(r4, addr);
                bv[kt][nh*2][0]   = r4[0]; bv[kt][nh*2][1]   = r4[1];
                bv[kt][nh*2+1][0] = r4[2]; bv[kt][nh*2+1][1] = r4[3];
            }

        const float* Tb = g_T + (((size_t)cls * NHEAD + h) << 12);

        #pragma unroll
        for (int mt = 0; mt < 4; mt++) {
            uint32_t aq[2][4];
            #pragma unroll
            for (int ks = 0; ks < 2; ks++) {
                const __half* qrow = qb + (mt * 16 + qr) * HD + ks * 16 + c0;
                aq[ks][0] = *(const uint32_t*)(qrow);
                aq[ks][1] = *(const uint32_t*)(qrow + 8 * HD);
                aq[ks][2] = *(const uint32_t*)(qrow + 8);
                aq[ks][3] = *(const uint32_t*)(qrow + 8 * HD + 8);
            }
            float sc[8][4];
            #pragma unroll
            for (int nt = 0; nt < 8; nt++)
                #pragma unroll
                for (int u = 0; u < 4; u++) sc[nt][u] = 0.f;

            #pragma unroll
            for (int ks = 0; ks < 2; ks++)
                #pragma unroll
                for (int np = 0; np < 4; np++) {
                    uint32_t r4[4];
                    uint32_t addr = sK + (uint32_t)((np * 16 + (lane & 7) + ((lane >> 4) << 3)) * 80
                                                    + (((lane >> 3) & 1) * 8 + ks * 16) * 2);
                    ldm4(r4, addr);
                    uint32_t b0[2] = { r4[0], r4[1] }, b1[2] = { r4[2], r4[3] };
                    mma16816(sc[2*np],     aq[ks], b0);
                    mma16816(sc[2*np + 1], aq[ks], b1);
                }

            const float* T0 = Tb + (mt * 16 + qr) * 64 + c0;
            const float* T1 = T0 + 8 * 64;
            float mx0 = -1e30f, mx1 = -1e30f;
            #pragma unroll
            for (int nt = 0; nt < 8; nt++) {
                float2 t0 = *(const float2*)(T0 + nt * 8);
                float2 t1 = *(const float2*)(T1 + nt * 8);
                sc[nt][0] += t0.x; sc[nt][1] += t0.y;
                sc[nt][2] += t1.x; sc[nt][3] += t1.y;
                mx0 = fmaxf(mx0, fmaxf(sc[nt][0], sc[nt][1]));
                mx1 = fmaxf(mx1, fmaxf(sc[nt][2], sc[nt][3]));
            }
            mx0 = fmaxf(mx0, __shfl_xor_sync(0xffffffffu, mx0, 1));
            mx0 = fmaxf(mx0, __shfl_xor_sync(0xffffffffu, mx0, 2));
            mx1 = fmaxf(mx1, __shfl_xor_sync(0xffffffffu, mx1, 1));
            mx1 = fmaxf(mx1, __shfl_xor_sync(0xffffffffu, mx1, 2));

            float s0 = 0.f, s1 = 0.f;
            uint32_t ph[8][2];
            #pragma unroll
            for (int nt = 0; nt < 8; nt++) {
                float e0 = __expf(sc[nt][0] - mx0);
                float e1 = __expf(sc[nt][1] - mx0);
                float e2 = __expf(sc[nt][2] - mx1);
                float e3 = __expf(sc[nt][3] - mx1);
                s0 += e0 + e1; s1 += e2 + e3;
                ph[nt][0] = packh2(e0, e1);
                ph[nt][1] = packh2(e2, e3);
            }
            s0 += __shfl_xor_sync(0xffffffffu, s0, 1);
            s0 += __shfl_xor_sync(0xffffffffu, s0, 2);
            s1 += __shfl_xor_sync(0xffffffffu, s1, 1);
            s1 += __shfl_xor_sync(0xffffffffu, s1, 2);

            float oa[4][4];
            #pragma unroll
            for (int n4 = 0; n4 < 4; n4++)
                #pragma unroll
                for (int u = 0; u < 4; u++) oa[n4][u] = 0.f;
            #pragma unroll
            for (int kt = 0; kt < 4; kt++) {
                uint32_t ap[4] = { ph[2*kt][0], ph[2*kt][1], ph[2*kt+1][0], ph[2*kt+1][1] };
                #pragma unroll
                for (int n4 = 0; n4 < 4; n4++) mma16816(oa[n4], ap, bv[kt][n4]);
            }

            float inv0 = 1.0f / s0, inv1 = 1.0f / s1;
            size_t ob0 = ((size_t)g * NTOK + mt * 16 + qr) * CC + h * HD;
            size_t ob1 = ob0 + (size_t)8 * CC;
            #pragma unroll
            for (int n4 = 0; n4 < 4; n4++) {
                int col = n4 * 8 + c0;
                *(uint32_t*)(g_ao + ob0 + col) = packh2(oa[n4][0] * inv0, oa[n4][1] * inv0);
                *(uint32_t*)(g_ao + ob1 + col) = packh2(oa[n4][2] * inv1, oa[n4][3] * inv1);
            }
        }
    }
}

// ---------------- launch ----------------
extern "C" void kernel_launch(void* const* d_in, const int* in_sizes, int n_in,
                              void* d_out, int out_size)
{
    const float* x          = (const float*)d_in[0];
    const float* g1         = (const float*)d_in[1];
    const float* b1         = (const float*)d_in[2];
    const float* Wqkv       = (const float*)d_in[3];
    const float* bqkv       = (const float*)d_in[4];
    const float* bias_table = (const float*)d_in[5];
    const float* Wp         = (const float*)d_in[6];
    const float* bp         = (const float*)d_in[7];
    const float* g2         = (const float*)d_in[8];
    const float* b2         = (const float*)d_in[9];
    const float* W1         = (const float*)d_in[10];
    const float* bb1        = (const float*)d_in[11];
    const float* W2         = (const float*)d_in[12];
    const float* bb2        = (const float*)d_in[13];
    float* out = (float*)d_out;

    const int SMEM = NSTAGE * STG_SZ;
    cudaFuncSetAttribute(tgemm<0, 3*CC, CC>,  cudaFuncAttributeMaxDynamicSharedMemorySize, SMEM);
    cudaFuncSetAttribute(tgemm<1, CC, CC>,    cudaFuncAttributeMaxDynamicSharedMemorySize, SMEM);
    cudaFuncSetAttribute(tgemm<2, HMLP, CC>,  cudaFuncAttributeMaxDynamicSharedMemorySize, SMEM);
    cudaFuncSetAttribute(tgemm<3, CC, HMLP>,  cudaFuncAttributeMaxDynamicSharedMemorySize, SMEM);
    cudaFuncSetAttribute(attn_kernel,         cudaFuncAttributeMaxDynamicSharedMemorySize, AT_SMEM);

    cvt_all<<<(NW3 + 255) / 256, 256>>>(Wqkv, Wp, W1, W2);
    build_T<<<dim3(8, NHEAD), 256>>>(bias_table);
    ln_kernel<0><<<TOK, 128>>>(x, g1, b1);
    tgemm<0, 3*CC, CC><<<dim3(3*CC/128, TOK/128), 256, SMEM>>>(bqkv, nullptr, nullptr);
    attn_kernel<<<NWIN, 128, AT_SMEM>>>();
    tgemm<1, CC, CC><<<dim3(CC/128, TOK/128), 256, SMEM>>>(bp, nullptr, x);
    ln_kernel<1><<<TOK, 128>>>(nullptr, g2, b2);
    tgemm<2, HMLP, CC><<<dim3(HMLP/128, TOK/128), 256, SMEM>>>(bb1, nullptr, nullptr);
    tgemm<3, CC, HMLP><<<dim3(CC/128, TOK/128), 256, SMEM>>>(bb2, out, nullptr);
}

// round 16
// speedup vs baseline: 1.1027x; 1.1027x over previous
#include <cuda_runtime.h>
#include <cuda_fp16.h>
#include <cstdint>

// ---------------- problem constants ----------------
#define CC 384
#define NHEAD 12
#define HD 32
#define NTOK 64
#define NWIN 1024
#define TOK 65536
#define HMLP 1536
#define QSCALE 0.17677669529663687f   // 32^-0.5

// ---------------- scratch (device globals; no allocations) ----------------
__device__ __half g_xw [TOK * CC];      // activations: fp16
__device__ __half g_ao [TOK * CC];
__device__ __half g_ln2[TOK * CC];
__device__ __half g_mlp[TOK * HMLP];
__device__ __half g_wqkv[3*CC*CC];      // weights: single fp16
__device__ __half g_wp [CC*CC];
__device__ __half g_w1 [HMLP*CC];
__device__ __half g_w2 [CC*HMLP];
__device__ __half g_q [TOK * CC];       // fp16 q (pre-scaled), k, v
__device__ __half g_k [TOK * CC];
__device__ __half g_v [TOK * CC];
__device__ float g_x2[TOK * CC];
__device__ float g_T [8 * NHEAD * NTOK * NTOK];   // bias+mask per window class

// ---------------- helpers ----------------
__device__ __forceinline__ uint32_t smem_u32(const void* p) {
    uint32_t a;
    asm("{ .reg .u64 t; cvta.to.shared.u64 t, %1; cvt.u32.u64 %0, t; }" : "=r"(a) : "l"(p));
    return a;
}
__device__ __forceinline__ void cp16(uint32_t saddr, const void* gaddr) {
    asm volatile("cp.async.cg.shared.global [%0], [%1], 16;" :: "r"(saddr), "l"(gaddr));
}
__device__ __forceinline__ void ldm4(uint32_t* r, uint32_t addr) {
    asm volatile("ldmatrix.sync.aligned.m8n8.x4.shared.b16 {%0,%1,%2,%3}, [%4];"
                 : "=r"(r[0]), "=r"(r[1]), "=r"(r[2]), "=r"(r[3]) : "r"(addr));
}
__device__ __forceinline__ void ldm4t(uint32_t* r, uint32_t addr) {
    asm volatile("ldmatrix.sync.aligned.m8n8.x4.trans.shared.b16 {%0,%1,%2,%3}, [%4];"
                 : "=r"(r[0]), "=r"(r[1]), "=r"(r[2]), "=r"(r[3]) : "r"(addr));
}
__device__ __forceinline__ void mma16816(float* c, const uint32_t* a, const uint32_t* b) {
    asm volatile("mma.sync.aligned.m16n8k16.row.col.f32.f16.f16.f32 "
                 "{%0,%1,%2,%3}, {%4,%5,%6,%7}, {%8,%9}, {%0,%1,%2,%3};"
                 : "+f"(c[0]), "+f"(c[1]), "+f"(c[2]), "+f"(c[3])
                 : "r"(a[0]), "r"(a[1]), "r"(a[2]), "r"(a[3]), "r"(b[0]), "r"(b[1]));
}
__device__ __forceinline__ uint32_t packh2(float a, float b) {
    __half2 h = __floats2half2_rn(a, b);
    return *(uint32_t*)&h;
}

// ---------------- fused weight fp32 -> fp16 ----------
#define NW0 (3*CC*CC)
#define NW1 (NW0 + CC*CC)
#define NW2 (NW1 + HMLP*CC)
#define NW3 (NW2 + CC*HMLP)
__global__ __launch_bounds__(256) void cvt_all(const float* __restrict__ wqkv,
                                               const float* __restrict__ wp,
                                               const float* __restrict__ w1,
                                               const float* __restrict__ w2) {
    int i = blockIdx.x * 256 + threadIdx.x;
    if (i >= NW3) return;
    const float* src; __half* dh; int o;
    if (i < NW0)      { src = wqkv; dh = g_wqkv; o = i; }
    else if (i < NW1) { src = wp;   dh = g_wp;   o = i - NW0; }
    else if (i < NW2) { src = w1;   dh = g_w1;   o = i - NW1; }
    else              { src = w2;   dh = g_w2;   o = i - NW2; }
    dh[o] = __float2half_rn(src[o]);
}

// ---------------- bias+mask table: T[cls][h][q][k] ----------
__global__ __launch_bounds__(256) void build_T(const float* __restrict__ bt) {
    int cls = blockIdx.x, h = blockIdx.y;
    bool bd = cls & 4, bh = cls & 2, bw = cls & 1;
    for (int e = threadIdx.x; e < NTOK * NTOK; e += 256) {
        int q = e >> 6, k = e & 63;
        int i = q >> 4, j = (q >> 2) & 3, kk = q & 3;
        int i2 = k >> 4, j2 = (k >> 2) & 3, k2 = k & 3;
        int idx = (i - i2 + 3) * 49 + (j - j2 + 3) * 7 + (kk - k2 + 3);
        bool m = (!bd || ((i < 2) == (i2 < 2))) &&
                 (!bh || ((j < 2) == (j2 < 2))) &&
                 (!bw || ((kk < 2) == (k2 < 2)));
        g_T[(((size_t)cls * NHEAD + h) << 12) + e] = bt[idx * NHEAD + h] + (m ? 0.f : -100.f);
    }
}

// ---------------- LayerNorm: 2 tokens per 256-thread block ----------------
template<int MODE>
__global__ __launch_bounds__(256) void ln_kernel(const float* __restrict__ xin,
                                                 const float* __restrict__ gamma,
                                                 const float* __restrict__ beta)
{
    int half = threadIdx.x >> 7;            // which token within the block
    int tid  = threadIdx.x & 127;
    int t = blockIdx.x * 2 + half;
    const float* src;
    __half* dh;
    if constexpr (MODE == 0) {
        int g = t >> 6, n = t & 63;
        int b = g >> 9, wd = (g >> 6) & 7, wh = (g >> 3) & 7, ww = g & 7;
        int i = n >> 4, j = (n >> 2) & 3, k = n & 3;
        int d0 = (wd * 4 + i + 2) & 31;
        int h0 = (wh * 4 + j + 2) & 31;
        int w0 = (ww * 4 + k + 2) & 31;
        src = xin + (size_t)(((b * 32 + d0) * 32 + h0) * 32 + w0) * CC;
        dh = g_xw + (size_t)t * CC;
    } else {
        src = g_x2 + (size_t)t * CC;
        dh = g_ln2 + (size_t)t * CC;
    }
    float v0 = src[tid], v1 = src[tid + 128], v2 = src[tid + 256];
    float s = v0 + v1 + v2;
    float ss = v0 * v0 + v1 * v1 + v2 * v2;
    #pragma unroll
    for (int o = 16; o > 0; o >>= 1) {
        s  += __shfl_xor_sync(0xffffffffu, s, o);
        ss += __shfl_xor_sync(0xffffffffu, ss, o);
    }
    __shared__ float red[2][8];
    if ((tid & 31) == 0) { red[half][tid >> 5] = s; red[half][4 + (tid >> 5)] = ss; }
    __syncthreads();
    s  = red[half][0] + red[half][1] + red[half][2] + red[half][3];
    ss = red[half][4] + red[half][5] + red[half][6] + red[half][7];
    float mu  = s * (1.0f / CC);
    float var = ss * (1.0f / CC) - mu * mu;
    float inv = rsqrtf(var + 1e-5f);
    dh[tid]       = __float2half_rn((v0 - mu) * inv * gamma[tid]       + beta[tid]);
    dh[tid + 128] = __float2half_rn((v1 - mu) * inv * gamma[tid + 128] + beta[tid + 128]);
    dh[tid + 256] = __float2half_rn((v2 - mu) * inv * gamma[tid + 256] + beta[tid + 256]);
}

// ---------------- mma.sync fp16 GEMM: C = A @ B^T + bias ------
// 128x128 CTA tile, BK=32, 3-stage cp.async ring; 2 CTAs/SM. (R10/R14 config)
#define STG_A   0
#define STG_B   10240
#define STG_SZ  20480
#define NSTAGE  3

template<int EPI, int N, int K>
__global__ __launch_bounds__(256, 2) void tgemm(const float* __restrict__ bias,
                                                float* __restrict__ Cout,
                                                const float* __restrict__ extra)
{
    const __half *A, *B;
    if constexpr (EPI == 0)      { A = g_xw;  B = g_wqkv; }
    else if constexpr (EPI == 1) { A = g_ao;  B = g_wp;   }
    else if constexpr (EPI == 2) { A = g_ln2; B = g_w1;   }
    else                         { A = g_mlp; B = g_w2;   }

    extern __shared__ char smem[];
    const uint32_t sb = smem_u32(smem);
    const int tid = threadIdx.x;
    const int wid = tid >> 5, lane = tid & 31;
    const int wm = wid & 1, wn = wid >> 1;
    const int m0 = blockIdx.y * 128, n0 = blockIdx.x * 128;
    constexpr int NC = K / 32;

    auto issue = [&](int c, int st) {
        int k0 = c * 32;
        uint32_t base = sb + (uint32_t)st * STG_SZ;
        #pragma unroll
        for (int t = 0; t < 2; t++) {
            int e = tid + t * 256;
            int r = e >> 2, cv = e & 3;
            uint32_t so = (uint32_t)(r * 80 + cv * 16);
            size_t ga = (size_t)(m0 + r) * K + k0 + cv * 8;
            size_t gb = (size_t)(n0 + r) * K + k0 + cv * 8;
            cp16(base + STG_A + so, A + ga);
            cp16(base + STG_B + so, B + gb);
        }
        asm volatile("cp.async.commit_group;");
    };

    const int lr = lane & 7;
    const int aRow = wm * 64 + lr + ((lane >> 3) & 1) * 8;
    const int aK   = (lane >> 4) * 8;
    const int bRow = wn * 32 + lr + (lane >> 4) * 8;
    const int bK   = ((lane >> 3) & 1) * 8;

    float acc[4][4][4];
    #pragma unroll
    for (int a = 0; a < 4; a++)
        #pragma unroll
        for (int b = 0; b < 4; b++)
            #pragma unroll
            for (int c = 0; c < 4; c++) acc[a][b][c] = 0.f;

    issue(0, 0);
    issue(1, 1);

    for (int c = 0; c < NC; c++) {
        if (c == NC - 1) asm volatile("cp.async.wait_group 0;");
        else             asm volatile("cp.async.wait_group 1;");
        __syncthreads();
        if (c + 2 < NC) issue(c + 2, (c + 2) % NSTAGE);

        uint32_t base = sb + (uint32_t)(c % NSTAGE) * STG_SZ;
        #pragma unroll
        for (int ks = 0; ks < 2; ks++) {
            uint32_t a_r[4][4];
            #pragma unroll
            for (int mt = 0; mt < 4; mt++) {
                uint32_t off = (uint32_t)((aRow + mt * 16) * 40 + ks * 16 + aK) * 2;
                ldm4(a_r[mt], base + STG_A + off);
            }
            uint32_t b_r[4][2];
            #pragma unroll
            for (int p = 0; p < 2; p++) {
                uint32_t off = (uint32_t)((bRow + p * 16) * 40 + ks * 16 + bK) * 2;
                uint32_t r4[4];
                ldm4(r4, base + STG_B + off);
                b_r[2*p][0] = r4[0]; b_r[2*p][1] = r4[1];
                b_r[2*p+1][0] = r4[2]; b_r[2*p+1][1] = r4[3];
            }
            #pragma unroll
            for (int mt = 0; mt < 4; mt++)
                #pragma unroll
                for (int nt = 0; nt < 4; nt++) mma16816(acc[mt][nt], a_r[mt], b_r[nt]);
        }
    }

    // ---------------- epilogue ----------------
    const int mrow0 = m0 + wm * 64 + (lane >> 2);
    const int ncol0 = n0 + wn * 32 + (lane & 3) * 2;

    #pragma unroll
    for (int mt = 0; mt < 4; mt++) {
        #pragma unroll
        for (int nt = 0; nt < 4; nt++) {
            #pragma unroll
            for (int half = 0; half < 2; half++) {
                int row = mrow0 + mt * 16 + half * 8;
                int col = ncol0 + nt * 8;
                float v0 = acc[mt][nt][half * 2]     + bias[col];
                float v1 = acc[mt][nt][half * 2 + 1] + bias[col + 1];

                if constexpr (EPI == 0) {
                    int s = col / CC; int rr = col - s * CC;
                    int hh = rr >> 5, d = rr & 31;
                    __half* dst = (s == 0) ? g_q : (s == 1) ? g_k : g_v;
                    if (s == 0) { v0 *= QSCALE; v1 *= QSCALE; }
                    size_t o = (((size_t)(row >> 6) * NHEAD + hh) * NTOK + (row & 63)) * HD + d;
                    *(uint32_t*)(dst + o) = packh2(v0, v1);
                } else if constexpr (EPI == 1) {
                    int g = row >> 6, nn = row & 63;
                    int b = g >> 9, wd = (g >> 6) & 7, wh = (g >> 3) & 7, ww = g & 7;
                    int i3 = nn >> 4, j3 = (nn >> 2) & 3, k3 = nn & 3;
                    int d0 = (wd * 4 + i3 + 2) & 31;
                    int h0 = (wh * 4 + j3 + 2) & 31;
                    int w0 = (ww * 4 + k3 + 2) & 31;
                    size_t nat = (size_t)(((b * 32 + d0) * 32 + h0) * 32 + w0) * CC + col;
                    float2 e = *(const float2*)(extra + nat);
                    *(float2*)(g_x2 + nat) = make_float2(v0 + e.x, v1 + e.y);
                } else if constexpr (EPI == 2) {
                    size_t o = (size_t)row * HMLP + col;
                    float t0 = v0 * 0.5f * (1.0f + erff(v0 * 0.70710678118654752f));
                    float t1 = v1 * 0.5f * (1.0f + erff(v1 * 0.70710678118654752f));
                    *(uint32_t*)(g_mlp + o) = packh2(t0, t1);
                } else {
                    size_t o = (size_t)row * CC + col;
                    float2 e = *(const float2*)(g_x2 + o);
                    *(float2*)(Cout + o) = make_float2(v0 + e.x, v1 + e.y);
                }
            }
        }
    }
}

// ---------------- mma attention: 1 block = 1 window, 4 warps x 3 heads -----
// K/V staged in warp-private smem; Q fragments loaded directly from global.
#define AT_WSZ  10240   // per-warp smem: K + V (2 x 64x40 halves)
#define AT_SMEM (4 * AT_WSZ)

__global__ __launch_bounds__(128) void attn_kernel()
{
    extern __shared__ char asmem[];
    int g = blockIdx.x;
    int tid = threadIdx.x, w = tid >> 5, lane = tid & 31;
    int wd = (g >> 6) & 7, wh = (g >> 3) & 7, ww = g & 7;
    int cls = ((wd == 7) << 2) | ((wh == 7) << 1) | (ww == 7);
    uint32_t wb = smem_u32(asmem) + (uint32_t)w * AT_WSZ;
    uint32_t sK = wb, sV = wb + 5120;

    const int qr = lane >> 2;
    const int c0 = (lane & 3) * 2;

    for (int hh = 0; hh < 3; hh++) {
        int h = w * 3 + hh;
        const __half* qb = g_q + (size_t)(g * NHEAD + h) * NTOK * HD;
        const __half* kb = g_k + (size_t)(g * NHEAD + h) * NTOK * HD;
        const __half* vb = g_v + (size_t)(g * NHEAD + h) * NTOK * HD;
        #pragma unroll
        for (int t = 0; t < 8; t++) {
            int e = lane + t * 32;
            int r = e >> 2, c = e & 3;
            cp16(sK + r * 80 + c * 16, kb + r * 32 + c * 8);
            cp16(sV + r * 80 + c * 16, vb + r * 32 + c * 8);
        }
        asm volatile("cp.async.commit_group;");
        asm volatile("cp.async.wait_group 0;");
        __syncwarp();

        uint32_t bv[4][4][2];
        #pragma unroll
        for (int kt = 0; kt < 4; kt++)
            #pragma unroll
            for (int nh = 0; nh < 2; nh++) {
                uint32_t r4[4];
                uint32_t addr = sV + (uint32_t)((kt * 16 + (lane & 15)) * 80
                                                + (nh * 16 + (lane >> 4) * 8) * 2);
                ldm4t(r4, addr);
                bv[kt][nh*2][0]   = r4[0]; bv[kt][nh*2][1]   = r4[1];
                bv[kt][nh*2+1][0] = r4[2]; bv[kt][nh*2+1][1] = r4[3];
            }

        const float* Tb = g_T + (((size_t)cls * NHEAD + h) << 12);

        #pragma unroll
        for (int mt = 0; mt < 4; mt++) {
            uint32_t aq[2][4];
            #pragma unroll
            for (int ks = 0; ks < 2; ks++) {
                const __half* qrow = qb + (mt * 16 + qr) * HD + ks * 16 + c0;
                aq[ks][0] = *(const uint32_t*)(qrow);
                aq[ks][1] = *(const uint32_t*)(qrow + 8 * HD);
                aq[ks][2] = *(const uint32_t*)(qrow + 8);
                aq[ks][3] = *(const uint32_t*)(qrow + 8 * HD + 8);
            }
            float sc[8][4];
            #pragma unroll
            for (int nt = 0; nt < 8; nt++)
                #pragma unroll
                for (int u = 0; u < 4; u++) sc[nt][u] = 0.f;

            #pragma unroll
            for (int ks = 0; ks < 2; ks++)
                #pragma unroll
                for (int np = 0; np < 4; np++) {
                    uint32_t r4[4];
                    uint32_t addr = sK + (uint32_t)((np * 16 + (lane & 7) + ((lane >> 4) << 3)) * 80
                                                    + (((lane >> 3) & 1) * 8 + ks * 16) * 2);
                    ldm4(r4, addr);
                    uint32_t b0[2] = { r4[0], r4[1] }, b1[2] = { r4[2], r4[3] };
                    mma16816(sc[2*np],     aq[ks], b0);
                    mma16816(sc[2*np + 1], aq[ks], b1);
                }

            const float* T0 = Tb + (mt * 16 + qr) * 64 + c0;
            const float* T1 = T0 + 8 * 64;
            float mx0 = -1e30f, mx1 = -1e30f;
            #pragma unroll
            for (int nt = 0; nt < 8; nt++) {
                float2 t0 = *(const float2*)(T0 + nt * 8);
                float2 t1 = *(const float2*)(T1 + nt * 8);
                sc[nt][0] += t0.x; sc[nt][1] += t0.y;
                sc[nt][2] += t1.x; sc[nt][3] += t1.y;
                mx0 = fmaxf(mx0, fmaxf(sc[nt][0], sc[nt][1]));
                mx1 = fmaxf(mx1, fmaxf(sc[nt][2], sc[nt][3]));
            }
            mx0 = fmaxf(mx0, __shfl_xor_sync(0xffffffffu, mx0, 1));
            mx0 = fmaxf(mx0, __shfl_xor_sync(0xffffffffu, mx0, 2));
            mx1 = fmaxf(mx1, __shfl_xor_sync(0xffffffffu, mx1, 1));
            mx1 = fmaxf(mx1, __shfl_xor_sync(0xffffffffu, mx1, 2));

            float s0 = 0.f, s1 = 0.f;
            uint32_t ph[8][2];
            #pragma unroll
            for (int nt = 0; nt < 8; nt++) {
                float e0 = __expf(sc[nt][0] - mx0);
                float e1 = __expf(sc[nt][1] - mx0);
                float e2 = __expf(sc[nt][2] - mx1);
                float e3 = __expf(sc[nt][3] - mx1);
                s0 += e0 + e1; s1 += e2 + e3;
                ph[nt][0] = packh2(e0, e1);
                ph[nt][1] = packh2(e2, e3);
            }
            s0 += __shfl_xor_sync(0xffffffffu, s0, 1);
            s0 += __shfl_xor_sync(0xffffffffu, s0, 2);
            s1 += __shfl_xor_sync(0xffffffffu, s1, 1);
            s1 += __shfl_xor_sync(0xffffffffu, s1, 2);

            float oa[4][4];
            #pragma unroll
            for (int n4 = 0; n4 < 4; n4++)
                #pragma unroll
                for (int u = 0; u < 4; u++) oa[n4][u] = 0.f;
            #pragma unroll
            for (int kt = 0; kt < 4; kt++) {
                uint32_t ap[4] = { ph[2*kt][0], ph[2*kt][1], ph[2*kt+1][0], ph[2*kt+1][1] };
                #pragma unroll
                for (int n4 = 0; n4 < 4; n4++) mma16816(oa[n4], ap, bv[kt][n4]);
            }

            float inv0 = 1.0f / s0, inv1 = 1.0f / s1;
            size_t ob0 = ((size_t)g * NTOK + mt * 16 + qr) * CC + h * HD;
            size_t ob1 = ob0 + (size_t)8 * CC;
            #pragma unroll
            for (int n4 = 0; n4 < 4; n4++) {
                int col = n4 * 8 + c0;
                *(uint32_t*)(g_ao + ob0 + col) = packh2(oa[n4][0] * inv0, oa[n4][1] * inv0);
                *(uint32_t*)(g_ao + ob1 + col) = packh2(oa[n4][2] * inv1, oa[n4][3] * inv1);
            }
        }
    }
}

// ---------------- launch ----------------
extern "C" void kernel_launch(void* const* d_in, const int* in_sizes, int n_in,
                              void* d_out, int out_size)
{
    const float* x          = (const float*)d_in[0];
    const float* g1         = (const float*)d_in[1];
    const float* b1         = (const float*)d_in[2];
    const float* Wqkv       = (const float*)d_in[3];
    const float* bqkv       = (const float*)d_in[4];
    const float* bias_table = (const float*)d_in[5];
    const float* Wp         = (const float*)d_in[6];
    const float* bp         = (const float*)d_in[7];
    const float* g2         = (const float*)d_in[8];
    const float* b2         = (const float*)d_in[9];
    const float* W1         = (const float*)d_in[10];
    const float* bb1        = (const float*)d_in[11];
    const float* W2         = (const float*)d_in[12];
    const float* bb2        = (const float*)d_in[13];
    float* out = (float*)d_out;

    const int SMEM = NSTAGE * STG_SZ;
    cudaFuncSetAttribute(tgemm<0, 3*CC, CC>,  cudaFuncAttributeMaxDynamicSharedMemorySize, SMEM);
    cudaFuncSetAttribute(tgemm<1, CC, CC>,    cudaFuncAttributeMaxDynamicSharedMemorySize, SMEM);
    cudaFuncSetAttribute(tgemm<2, HMLP, CC>,  cudaFuncAttributeMaxDynamicSharedMemorySize, SMEM);
    cudaFuncSetAttribute(tgemm<3, CC, HMLP>,  cudaFuncAttributeMaxDynamicSharedMemorySize, SMEM);
    cudaFuncSetAttribute(attn_kernel,         cudaFuncAttributeMaxDynamicSharedMemorySize, AT_SMEM);

    cvt_all<<<(NW3 + 255) / 256, 256>>>(Wqkv, Wp, W1, W2);
    build_T<<<dim3(8, NHEAD), 256>>>(bias_table);
    ln_kernel<0><<<TOK / 2, 256>>>(x, g1, b1);
    tgemm<0, 3*CC, CC><<<dim3(3*CC/128, TOK/128), 256, SMEM>>>(bqkv, nullptr, nullptr);
    attn_kernel<<<NWIN, 128, AT_SMEM>>>();
    tgemm<1, CC, CC><<<dim3(CC/128, TOK/128), 256, SMEM>>>(bp, nullptr, x);
    ln_kernel<1><<<TOK / 2, 256>>>(nullptr, g2, b2);
    tgemm<2, HMLP, CC><<<dim3(HMLP/128, TOK/128), 256, SMEM>>>(bb1, nullptr, nullptr);
    tgemm<3, CC, HMLP><<<dim3(CC/128, TOK/128), 256, SMEM>>>(bb2, out, nullptr);
}

// round 17
// speedup vs baseline: 1.1064x; 1.0034x over previous
#include <cuda_runtime.h>
#include <cuda_fp16.h>
#include <cstdint>

// ---------------- problem constants ----------------
#define CC 384
#define NHEAD 12
#define HD 32
#define NTOK 64
#define NWIN 1024
#define TOK 65536
#define HMLP 1536
#define QSCALE 0.17677669529663687f   // 32^-0.5

// ---------------- scratch (device globals; no allocations) ----------------
__device__ __half g_xw [TOK * CC];      // activations: fp16
__device__ __half g_ao [TOK * CC];
__device__ __half g_ln2[TOK * CC];
__device__ __half g_mlp[TOK * HMLP];
__device__ __half g_wqkv[3*CC*CC];      // weights: single fp16
__device__ __half g_wp [CC*CC];
__device__ __half g_w1 [HMLP*CC];
__device__ __half g_w2 [CC*HMLP];
__device__ __half g_q [TOK * CC];       // fp16 q (pre-scaled), k, v
__device__ __half g_k [TOK * CC];
__device__ __half g_v [TOK * CC];
__device__ float g_x2[TOK * CC];
__device__ float g_T [8 * NHEAD * NTOK * NTOK];   // bias+mask per window class

// ---------------- helpers ----------------
__device__ __forceinline__ uint32_t smem_u32(const void* p) {
    uint32_t a;
    asm("{ .reg .u64 t; cvta.to.shared.u64 t, %1; cvt.u32.u64 %0, t; }" : "=r"(a) : "l"(p));
    return a;
}
__device__ __forceinline__ void cp16(uint32_t saddr, const void* gaddr) {
    asm volatile("cp.async.cg.shared.global [%0], [%1], 16;" :: "r"(saddr), "l"(gaddr));
}
__device__ __forceinline__ void ldm4(uint32_t* r, uint32_t addr) {
    asm volatile("ldmatrix.sync.aligned.m8n8.x4.shared.b16 {%0,%1,%2,%3}, [%4];"
                 : "=r"(r[0]), "=r"(r[1]), "=r"(r[2]), "=r"(r[3]) : "r"(addr));
}
__device__ __forceinline__ void ldm4t(uint32_t* r, uint32_t addr) {
    asm volatile("ldmatrix.sync.aligned.m8n8.x4.trans.shared.b16 {%0,%1,%2,%3}, [%4];"
                 : "=r"(r[0]), "=r"(r[1]), "=r"(r[2]), "=r"(r[3]) : "r"(addr));
}
__device__ __forceinline__ void mma16816(float* c, const uint32_t* a, const uint32_t* b) {
    asm volatile("mma.sync.aligned.m16n8k16.row.col.f32.f16.f16.f32 "
                 "{%0,%1,%2,%3}, {%4,%5,%6,%7}, {%8,%9}, {%0,%1,%2,%3};"
                 : "+f"(c[0]), "+f"(c[1]), "+f"(c[2]), "+f"(c[3])
                 : "r"(a[0]), "r"(a[1]), "r"(a[2]), "r"(a[3]), "r"(b[0]), "r"(b[1]));
}
__device__ __forceinline__ uint32_t packh2(float a, float b) {
    __half2 h = __floats2half2_rn(a, b);
    return *(uint32_t*)&h;
}

// ---------------- fused setup: weight fp32->fp16 + bias/mask table ---------
#define NW0 (3*CC*CC)
#define NW1 (NW0 + CC*CC)
#define NW2 (NW1 + HMLP*CC)
#define NW3 (NW2 + CC*HMLP)
#define CVT_BLOCKS ((NW3 + 255) / 256)

__global__ __launch_bounds__(256) void setup_all(const float* __restrict__ wqkv,
                                                 const float* __restrict__ wp,
                                                 const float* __restrict__ w1,
                                                 const float* __restrict__ w2,
                                                 const float* __restrict__ bt) {
    int b = blockIdx.x;
    if (b < CVT_BLOCKS) {
        int i = b * 256 + threadIdx.x;
        if (i >= NW3) return;
        const float* src; __half* dh; int o;
        if (i < NW0)      { src = wqkv; dh = g_wqkv; o = i; }
        else if (i < NW1) { src = wp;   dh = g_wp;   o = i - NW0; }
        else if (i < NW2) { src = w1;   dh = g_w1;   o = i - NW1; }
        else              { src = w2;   dh = g_w2;   o = i - NW2; }
        dh[o] = __float2half_rn(src[o]);
    } else {
        int tb = b - CVT_BLOCKS;          // 0..95
        int cls = tb / NHEAD, h = tb % NHEAD;
        bool bd = cls & 4, bh = cls & 2, bw = cls & 1;
        for (int e = threadIdx.x; e < NTOK * NTOK; e += 256) {
            int q = e >> 6, k = e & 63;
            int i = q >> 4, j = (q >> 2) & 3, kk = q & 3;
            int i2 = k >> 4, j2 = (k >> 2) & 3, k2 = k & 3;
            int idx = (i - i2 + 3) * 49 + (j - j2 + 3) * 7 + (kk - k2 + 3);
            bool m = (!bd || ((i < 2) == (i2 < 2))) &&
                     (!bh || ((j < 2) == (j2 < 2))) &&
                     (!bw || ((kk < 2) == (k2 < 2)));
            g_T[(((size_t)cls * NHEAD + h) << 12) + e] = bt[idx * NHEAD + h] + (m ? 0.f : -100.f);
        }
    }
}

// ---------------- LayerNorm (R14 config: 128 thr, 1 token/block) ----------
template<int MODE>
__global__ __launch_bounds__(128) void ln_kernel(const float* __restrict__ xin,
                                                 const float* __restrict__ gamma,
                                                 const float* __restrict__ beta)
{
    int t = blockIdx.x;
    const float* src;
    __half* dh;
    if constexpr (MODE == 0) {
        int g = t >> 6, n = t & 63;
        int b = g >> 9, wd = (g >> 6) & 7, wh = (g >> 3) & 7, ww = g & 7;
        int i = n >> 4, j = (n >> 2) & 3, k = n & 3;
        int d0 = (wd * 4 + i + 2) & 31;
        int h0 = (wh * 4 + j + 2) & 31;
        int w0 = (ww * 4 + k + 2) & 31;
        src = xin + (size_t)(((b * 32 + d0) * 32 + h0) * 32 + w0) * CC;
        dh = g_xw + (size_t)t * CC;
    } else {
        src = g_x2 + (size_t)t * CC;
        dh = g_ln2 + (size_t)t * CC;
    }
    int tid = threadIdx.x;
    float v0 = src[tid], v1 = src[tid + 128], v2 = src[tid + 256];
    float s = v0 + v1 + v2;
    float ss = v0 * v0 + v1 * v1 + v2 * v2;
    #pragma unroll
    for (int o = 16; o > 0; o >>= 1) {
        s  += __shfl_xor_sync(0xffffffffu, s, o);
        ss += __shfl_xor_sync(0xffffffffu, ss, o);
    }
    __shared__ float red[8];
    if ((tid & 31) == 0) { red[tid >> 5] = s; red[4 + (tid >> 5)] = ss; }
    __syncthreads();
    s  = red[0] + red[1] + red[2] + red[3];
    ss = red[4] + red[5] + red[6] + red[7];
    float mu  = s * (1.0f / CC);
    float var = ss * (1.0f / CC) - mu * mu;
    float inv = rsqrtf(var + 1e-5f);
    dh[tid]       = __float2half_rn((v0 - mu) * inv * gamma[tid]       + beta[tid]);
    dh[tid + 128] = __float2half_rn((v1 - mu) * inv * gamma[tid + 128] + beta[tid + 128]);
    dh[tid + 256] = __float2half_rn((v2 - mu) * inv * gamma[tid + 256] + beta[tid + 256]);
}

// ---------------- mma.sync fp16 GEMM: C = A @ B^T + bias ------
// 128x128 CTA tile, BK=32, 3-stage cp.async ring; 2 CTAs/SM. (R10/R14 config)
#define STG_A   0
#define STG_B   10240
#define STG_SZ  20480
#define NSTAGE  3

template<int EPI, int N, int K>
__global__ __launch_bounds__(256, 2) void tgemm(const float* __restrict__ bias,
                                                float* __restrict__ Cout,
                                                const float* __restrict__ extra)
{
    const __half *A, *B;
    if constexpr (EPI == 0)      { A = g_xw;  B = g_wqkv; }
    else if constexpr (EPI == 1) { A = g_ao;  B = g_wp;   }
    else if constexpr (EPI == 2) { A = g_ln2; B = g_w1;   }
    else                         { A = g_mlp; B = g_w2;   }

    extern __shared__ char smem[];
    const uint32_t sb = smem_u32(smem);
    const int tid = threadIdx.x;
    const int wid = tid >> 5, lane = tid & 31;
    const int wm = wid & 1, wn = wid >> 1;
    const int m0 = blockIdx.y * 128, n0 = blockIdx.x * 128;
    constexpr int NC = K / 32;

    auto issue = [&](int c, int st) {
        int k0 = c * 32;
        uint32_t base = sb + (uint32_t)st * STG_SZ;
        #pragma unroll
        for (int t = 0; t < 2; t++) {
            int e = tid + t * 256;
            int r = e >> 2, cv = e & 3;
            uint32_t so = (uint32_t)(r * 80 + cv * 16);
            size_t ga = (size_t)(m0 + r) * K + k0 + cv * 8;
            size_t gb = (size_t)(n0 + r) * K + k0 + cv * 8;
            cp16(base + STG_A + so, A + ga);
            cp16(base + STG_B + so, B + gb);
        }
        asm volatile("cp.async.commit_group;");
    };

    const int lr = lane & 7;
    const int aRow = wm * 64 + lr + ((lane >> 3) & 1) * 8;
    const int aK   = (lane >> 4) * 8;
    const int bRow = wn * 32 + lr + (lane >> 4) * 8;
    const int bK   = ((lane >> 3) & 1) * 8;

    float acc[4][4][4];
    #pragma unroll
    for (int a = 0; a < 4; a++)
        #pragma unroll
        for (int b = 0; b < 4; b++)
            #pragma unroll
            for (int c = 0; c < 4; c++) acc[a][b][c] = 0.f;

    issue(0, 0);
    issue(1, 1);

    for (int c = 0; c < NC; c++) {
        if (c == NC - 1) asm volatile("cp.async.wait_group 0;");
        else             asm volatile("cp.async.wait_group 1;");
        __syncthreads();
        if (c + 2 < NC) issue(c + 2, (c + 2) % NSTAGE);

        uint32_t base = sb + (uint32_t)(c % NSTAGE) * STG_SZ;
        #pragma unroll
        for (int ks = 0; ks < 2; ks++) {
            uint32_t a_r[4][4];
            #pragma unroll
            for (int mt = 0; mt < 4; mt++) {
                uint32_t off = (uint32_t)((aRow + mt * 16) * 40 + ks * 16 + aK) * 2;
                ldm4(a_r[mt], base + STG_A + off);
            }
            uint32_t b_r[4][2];
            #pragma unroll
            for (int p = 0; p < 2; p++) {
                uint32_t off = (uint32_t)((bRow + p * 16) * 40 + ks * 16 + bK) * 2;
                uint32_t r4[4];
                ldm4(r4, base + STG_B + off);
                b_r[2*p][0] = r4[0]; b_r[2*p][1] = r4[1];
                b_r[2*p+1][0] = r4[2]; b_r[2*p+1][1] = r4[3];
            }
            #pragma unroll
            for (int mt = 0; mt < 4; mt++)
                #pragma unroll
                for (int nt = 0; nt < 4; nt++) mma16816(acc[mt][nt], a_r[mt], b_r[nt]);
        }
    }

    // ---------------- epilogue ----------------
    const int mrow0 = m0 + wm * 64 + (lane >> 2);
    const int ncol0 = n0 + wn * 32 + (lane & 3) * 2;

    #pragma unroll
    for (int mt = 0; mt < 4; mt++) {
        #pragma unroll
        for (int nt = 0; nt < 4; nt++) {
            #pragma unroll
            for (int half = 0; half < 2; half++) {
                int row = mrow0 + mt * 16 + half * 8;
                int col = ncol0 + nt * 8;
                float v0 = acc[mt][nt][half * 2]     + bias[col];
                float v1 = acc[mt][nt][half * 2 + 1] + bias[col + 1];

                if constexpr (EPI == 0) {
                    int s = col / CC; int rr = col - s * CC;
                    int hh = rr >> 5, d = rr & 31;
                    __half* dst = (s == 0) ? g_q : (s == 1) ? g_k : g_v;
                    if (s == 0) { v0 *= QSCALE; v1 *= QSCALE; }
                    size_t o = (((size_t)(row >> 6) * NHEAD + hh) * NTOK + (row & 63)) * HD + d;
                    *(uint32_t*)(dst + o) = packh2(v0, v1);
                } else if constexpr (EPI == 1) {
                    int g = row >> 6, nn = row & 63;
                    int b = g >> 9, wd = (g >> 6) & 7, wh = (g >> 3) & 7, ww = g & 7;
                    int i3 = nn >> 4, j3 = (nn >> 2) & 3, k3 = nn & 3;
                    int d0 = (wd * 4 + i3 + 2) & 31;
                    int h0 = (wh * 4 + j3 + 2) & 31;
                    int w0 = (ww * 4 + k3 + 2) & 31;
                    size_t nat = (size_t)(((b * 32 + d0) * 32 + h0) * 32 + w0) * CC + col;
                    float2 e = *(const float2*)(extra + nat);
                    *(float2*)(g_x2 + nat) = make_float2(v0 + e.x, v1 + e.y);
                } else if constexpr (EPI == 2) {
                    size_t o = (size_t)row * HMLP + col;
                    float t0 = v0 * 0.5f * (1.0f + erff(v0 * 0.70710678118654752f));
                    float t1 = v1 * 0.5f * (1.0f + erff(v1 * 0.70710678118654752f));
                    *(uint32_t*)(g_mlp + o) = packh2(t0, t1);
                } else {
                    size_t o = (size_t)row * CC + col;
                    float2 e = *(const float2*)(g_x2 + o);
                    *(float2*)(Cout + o) = make_float2(v0 + e.x, v1 + e.y);
                }
            }
        }
    }
}

// ---------------- mma attention: 1 block = 1 window, 4 warps x 3 heads -----
// K/V staged in warp-private smem; Q fragments loaded directly from global.
#define AT_WSZ  10240   // per-warp smem: K + V (2 x 64x40 halves)
#define AT_SMEM (4 * AT_WSZ)

__global__ __launch_bounds__(128) void attn_kernel()
{
    extern __shared__ char asmem[];
    int g = blockIdx.x;
    int tid = threadIdx.x, w = tid >> 5, lane = tid & 31;
    int wd = (g >> 6) & 7, wh = (g >> 3) & 7, ww = g & 7;
    int cls = ((wd == 7) << 2) | ((wh == 7) << 1) | (ww == 7);
    uint32_t wb = smem_u32(asmem) + (uint32_t)w * AT_WSZ;
    uint32_t sK = wb, sV = wb + 5120;

    const int qr = lane >> 2;
    const int c0 = (lane & 3) * 2;

    for (int hh = 0; hh < 3; hh++) {
        int h = w * 3 + hh;
        const __half* qb = g_q + (size_t)(g * NHEAD + h) * NTOK * HD;
        const __half* kb = g_k + (size_t)(g * NHEAD + h) * NTOK * HD;
        const __half* vb = g_v + (size_t)(g * NHEAD + h) * NTOK * HD;
        #pragma unroll
        for (int t = 0; t < 8; t++) {
            int e = lane + t * 32;
            int r = e >> 2, c = e & 3;
            cp16(sK + r * 80 + c * 16, kb + r * 32 + c * 8);
            cp16(sV + r * 80 + c * 16, vb + r * 32 + c * 8);
        }
        asm volatile("cp.async.commit_group;");
        asm volatile("cp.async.wait_group 0;");
        __syncwarp();

        uint32_t bv[4][4][2];
        #pragma unroll
        for (int kt = 0; kt < 4; kt++)
            #pragma unroll
            for (int nh = 0; nh < 2; nh++) {
                uint32_t r4[4];
                uint32_t addr = sV + (uint32_t)((kt * 16 + (lane & 15)) * 80
                                                + (nh * 16 + (lane >> 4) * 8) * 2);
                ldm4t(r4, addr);
                bv[kt][nh*2][0]   = r4[0]; bv[kt][nh*2][1]   = r4[1];
                bv[kt][nh*2+1][0] = r4[2]; bv[kt][nh*2+1][1] = r4[3];
            }

        const float* Tb = g_T + (((size_t)cls * NHEAD + h) << 12);

        #pragma unroll
        for (int mt = 0; mt < 4; mt++) {
            uint32_t aq[2][4];
            #pragma unroll
            for (int ks = 0; ks < 2; ks++) {
                const __half* qrow = qb + (mt * 16 + qr) * HD + ks * 16 + c0;
                aq[ks][0] = *(const uint32_t*)(qrow);
                aq[ks][1] = *(const uint32_t*)(qrow + 8 * HD);
                aq[ks][2] = *(const uint32_t*)(qrow + 8);
                aq[ks][3] = *(const uint32_t*)(qrow + 8 * HD + 8);
            }
            float sc[8][4];
            #pragma unroll
            for (int nt = 0; nt < 8; nt++)
                #pragma unroll
                for (int u = 0; u < 4; u++) sc[nt][u] = 0.f;

            #pragma unroll
            for (int ks = 0; ks < 2; ks++)
                #pragma unroll
                for (int np = 0; np < 4; np++) {
                    uint32_t r4[4];
                    uint32_t addr = sK + (uint32_t)((np * 16 + (lane & 7) + ((lane >> 4) << 3)) * 80
                                                    + (((lane >> 3) & 1) * 8 + ks * 16) * 2);
                    ldm4(r4, addr);
                    uint32_t b0[2] = { r4[0], r4[1] }, b1[2] = { r4[2], r4[3] };
                    mma16816(sc[2*np],     aq[ks], b0);
                    mma16816(sc[2*np + 1], aq[ks], b1);
                }

            const float* T0 = Tb + (mt * 16 + qr) * 64 + c0;
            const float* T1 = T0 + 8 * 64;
            float mx0 = -1e30f, mx1 = -1e30f;
            #pragma unroll
            for (int nt = 0; nt < 8; nt++) {
                float2 t0 = *(const float2*)(T0 + nt * 8);
                float2 t1 = *(const float2*)(T1 + nt * 8);
                sc[nt][0] += t0.x; sc[nt][1] += t0.y;
                sc[nt][2] += t1.x; sc[nt][3] += t1.y;
                mx0 = fmaxf(mx0, fmaxf(sc[nt][0], sc[nt][1]));
                mx1 = fmaxf(mx1, fmaxf(sc[nt][2], sc[nt][3]));
            }
            mx0 = fmaxf(mx0, __shfl_xor_sync(0xffffffffu, mx0, 1));
            mx0 = fmaxf(mx0, __shfl_xor_sync(0xffffffffu, mx0, 2));
            mx1 = fmaxf(mx1, __shfl_xor_sync(0xffffffffu, mx1, 1));
            mx1 = fmaxf(mx1, __shfl_xor_sync(0xffffffffu, mx1, 2));

            float s0 = 0.f, s1 = 0.f;
            uint32_t ph[8][2];
            #pragma unroll
            for (int nt = 0; nt < 8; nt++) {
                float e0 = __expf(sc[nt][0] - mx0);
                float e1 = __expf(sc[nt][1] - mx0);
                float e2 = __expf(sc[nt][2] - mx1);
                float e3 = __expf(sc[nt][3] - mx1);
                s0 += e0 + e1; s1 += e2 + e3;
                ph[nt][0] = packh2(e0, e1);
                ph[nt][1] = packh2(e2, e3);
            }
            s0 += __shfl_xor_sync(0xffffffffu, s0, 1);
            s0 += __shfl_xor_sync(0xffffffffu, s0, 2);
            s1 += __shfl_xor_sync(0xffffffffu, s1, 1);
            s1 += __shfl_xor_sync(0xffffffffu, s1, 2);

            float oa[4][4];
            #pragma unroll
            for (int n4 = 0; n4 < 4; n4++)
                #pragma unroll
                for (int u = 0; u < 4; u++) oa[n4][u] = 0.f;
            #pragma unroll
            for (int kt = 0; kt < 4; kt++) {
                uint32_t ap[4] = { ph[2*kt][0], ph[2*kt][1], ph[2*kt+1][0], ph[2*kt+1][1] };
                #pragma unroll
                for (int n4 = 0; n4 < 4; n4++) mma16816(oa[n4], ap, bv[kt][n4]);
            }

            float inv0 = 1.0f / s0, inv1 = 1.0f / s1;
            size_t ob0 = ((size_t)g * NTOK + mt * 16 + qr) * CC + h * HD;
            size_t ob1 = ob0 + (size_t)8 * CC;
            #pragma unroll
            for (int n4 = 0; n4 < 4; n4++) {
                int col = n4 * 8 + c0;
                *(uint32_t*)(g_ao + ob0 + col) = packh2(oa[n4][0] * inv0, oa[n4][1] * inv0);
                *(uint32_t*)(g_ao + ob1 + col) = packh2(oa[n4][2] * inv1, oa[n4][3] * inv1);
            }
        }
    }
}

// ---------------- launch ----------------
extern "C" void kernel_launch(void* const* d_in, const int* in_sizes, int n_in,
                              void* d_out, int out_size)
{
    const float* x          = (const float*)d_in[0];
    const float* g1         = (const float*)d_in[1];
    const float* b1         = (const float*)d_in[2];
    const float* Wqkv       = (const float*)d_in[3];
    const float* bqkv       = (const float*)d_in[4];
    const float* bias_table = (const float*)d_in[5];
    const float* Wp         = (const float*)d_in[6];
    const float* bp         = (const float*)d_in[7];
    const float* g2         = (const float*)d_in[8];
    const float* b2         = (const float*)d_in[9];
    const float* W1         = (const float*)d_in[10];
    const float* bb1        = (const float*)d_in[11];
    const float* W2         = (const float*)d_in[12];
    const float* bb2        = (const float*)d_in[13];
    float* out = (float*)d_out;

    const int SMEM = NSTAGE * STG_SZ;
    cudaFuncSetAttribute(tgemm<0, 3*CC, CC>,  cudaFuncAttributeMaxDynamicSharedMemorySize, SMEM);
    cudaFuncSetAttribute(tgemm<1, CC, CC>,    cudaFuncAttributeMaxDynamicSharedMemorySize, SMEM);
    cudaFuncSetAttribute(tgemm<2, HMLP, CC>,  cudaFuncAttributeMaxDynamicSharedMemorySize, SMEM);
    cudaFuncSetAttribute(tgemm<3, CC, HMLP>,  cudaFuncAttributeMaxDynamicSharedMemorySize, SMEM);
    cudaFuncSetAttribute(attn_kernel,         cudaFuncAttributeMaxDynamicSharedMemorySize, AT_SMEM);

    setup_all<<<CVT_BLOCKS + 8 * NHEAD, 256>>>(Wqkv, Wp, W1, W2, bias_table);
    ln_kernel<0><<<TOK, 128>>>(x, g1, b1);
    tgemm<0, 3*CC, CC><<<dim3(3*CC/128, TOK/128), 256, SMEM>>>(bqkv, nullptr, nullptr);
    attn_kernel<<<NWIN, 128, AT_SMEM>>>();
    tgemm<1, CC, CC><<<dim3(CC/128, TOK/128), 256, SMEM>>>(bp, nullptr, x);
    ln_kernel<1><<<TOK, 128>>>(nullptr, g2, b2);
    tgemm<2, HMLP, CC><<<dim3(HMLP/128, TOK/128), 256, SMEM>>>(bb1, nullptr, nullptr);
    tgemm<3, CC, HMLP><<<dim3(CC/128, TOK/128), 256, SMEM>>>(bb2, out, nullptr);
}